// round 15
// baseline (speedup 1.0000x reference)
#include <cuda_runtime.h>
#include <cuda_bf16.h>
#include <mma.h>
#include <cstdint>

using namespace nvcuda;

// Problem constants (fixed by the dataset)
#define MAX_N 50000
#define MAX_E 800000
#define MAX_F 128

// GEMM tiling
#define WTM 128            // block tile M
#define WKC 32             // K chunk
#define ALD 40             // A smem row stride (bf16 elems, mult of 8)

// ---------------- scratch (static device globals) ----------------
__device__ __align__(16) int   g_degi[MAX_N];
__device__ __align__(16) float g_dinv[MAX_N];
__device__ __align__(16) int   g_rowptr[MAX_N + 1];
__device__ __align__(16) int   g_cursor[MAX_N];
__device__ __align__(16) int2  g_csr [MAX_E];     // .x = src, .y = bits(norm)
// g_h padded by one M-tile of rows: unguarded wmma stores of the last partial
// tile land in scratch pad, never beyond this array.
__device__ __align__(16) float g_h   [(size_t)(MAX_N + WTM) * MAX_F];
__device__ __align__(16) float g_agg [(size_t)MAX_N * MAX_F];
__device__ int g_is64;

// ---------------- dtype detection: int64 vs int32 edge_index ----------------
__global__ void k_detect(const int* __restrict__ ei32) {
    if (threadIdx.x || blockIdx.x) return;
    int is64 = 1;
    #pragma unroll 1
    for (int i = 0; i < 128; i++) {
        if (ei32[2 * i + 1] != 0) { is64 = 0; break; }
    }
    g_is64 = is64;
}

__device__ __forceinline__ int edge_id(const void* ei, size_t pos) {
    if (g_is64) return (int)((const long long*)ei)[pos];
    return ((const int*)ei)[pos];
}

// ---------------- degree / norm precompute ----------------
__global__ void k_zero_deg(int n) {
    int i = blockIdx.x * blockDim.x + threadIdx.x;
    if (i < n) g_degi[i] = 0;
}

__global__ void k_count_deg(const void* __restrict__ ei, int E) {
    int e = blockIdx.x * blockDim.x + threadIdx.x;
    if (e < E) atomicAdd(&g_degi[edge_id(ei, (size_t)E + e)], 1);
}

__global__ void k_dinv(int n) {
    int i = blockIdx.x * blockDim.x + threadIdx.x;
    if (i < n) g_dinv[i] = rsqrtf((float)g_degi[i] + 1.0f);
}

// ---------------- exclusive prefix scan of degrees -> row_ptr (single block) ----------------
__global__ __launch_bounds__(1024) void k_scan(int Nn) {
    __shared__ int warp_sums[32];
    __shared__ int carry_sh;
    int tid  = threadIdx.x;
    int lane = tid & 31;
    int wid  = tid >> 5;
    if (tid == 0) carry_sh = 0;
    __syncthreads();
    for (int base = 0; base < Nn; base += 1024) {
        int i = base + tid;
        int v = (i < Nn) ? g_degi[i] : 0;
        int s = v;
        #pragma unroll
        for (int o = 1; o < 32; o <<= 1) {
            int t = __shfl_up_sync(0xFFFFFFFFu, s, o);
            if (lane >= o) s += t;
        }
        if (lane == 31) warp_sums[wid] = s;
        __syncthreads();
        if (wid == 0) {
            int ws = warp_sums[lane];
            #pragma unroll
            for (int o = 1; o < 32; o <<= 1) {
                int t = __shfl_up_sync(0xFFFFFFFFu, ws, o);
                if (lane >= o) ws += t;
            }
            warp_sums[lane] = ws;   // inclusive over warps
        }
        __syncthreads();
        int warp_off = (wid == 0) ? 0 : warp_sums[wid - 1];
        int excl = carry_sh + warp_off + (s - v);
        if (i < Nn) { g_rowptr[i] = excl; g_cursor[i] = excl; }
        __syncthreads();
        if (tid == 0) carry_sh += warp_sums[31];
        __syncthreads();
    }
    if (tid == 0) g_rowptr[Nn] = carry_sh;
}

// ---------------- CSR build: one pass over edges -> counting-sorted CSR ----------------
__global__ void k_build(const void* __restrict__ ei, int E) {
    int e = blockIdx.x * blockDim.x + threadIdx.x;
    if (e >= E) return;
    int s = edge_id(ei, e);
    int d = edge_id(ei, (size_t)E + e);
    float nrm = g_dinv[s] * g_dinv[d];
    int pos = atomicAdd(&g_cursor[d], 1);
    int2 m;
    m.x = s;
    m.y = __float_as_int(nrm);
    g_csr[pos] = m;
}

// ---------------- GEMM: g_h[M,N] = act(A[M,K]) @ W[K,N], split-bf16 tensor cores ----
// a = hi + lo (bf16 split); acc += hi*Whi + hi*Wlo + lo*Whi in fp32.
// Block 128 x TN, 256 threads = 8 warps (4x2); warp tile 32 x TN/2.
// 2-stage double-buffered smem (dynamic), register prefetch, 1 sync per K-tile.
template<int TN>
__global__ __launch_bounds__(256) void k_gemm(const float* __restrict__ Ax,
                                              const float* __restrict__ W,
                                              int M, int K, int N, int aSel) {
    constexpr int BLD = TN + 8;                    // B smem row stride
    constexpr int ALOADS = (WTM * WKC / 4) / 256;  // 4 float4 per thread
    constexpr int BLOADS = (WKC * TN / 4) / 256;   // 4 (TN=128) / 2 (TN=64)
    constexpr int FN = TN / 32;                    // b-frags per warp
    constexpr int ASZ = 2 * WTM * ALD;             // elems per split-half
    constexpr int BSZ = 2 * WKC * BLD;

    extern __shared__ __nv_bfloat16 smem[];
    __nv_bfloat16* Ah = smem;
    __nv_bfloat16* Al = Ah + ASZ;
    __nv_bfloat16* Bh = Al + ASZ;
    __nv_bfloat16* Bl = Bh + BSZ;

    const float* A = aSel ? (const float*)g_agg : Ax;
    int tid  = threadIdx.x;
    int warp = tid >> 5;
    int wm   = warp >> 1;            // 0..3
    int wn   = warp & 1;             // 0..1
    int row0 = blockIdx.y * WTM;
    int col0 = blockIdx.x * TN;
    int K4   = K >> 2;
    int T    = K / WKC;

    wmma::fragment<wmma::accumulator, 16, 16, 16, float> acc[2][FN];
    #pragma unroll
    for (int i = 0; i < 2; i++)
        #pragma unroll
        for (int j = 0; j < FN; j++)
            wmma::fill_fragment(acc[i][j], 0.0f);

    float4 fa[ALOADS], fb[BLOADS];

    // ---- fetch tile kt into registers ----
    auto fetch = [&](int kt) {
        int kb4 = kt * (WKC / 4);
        #pragma unroll
        for (int i = 0; i < ALOADS; i++) {
            int q  = tid + i * 256;
            int m  = q >> 3;             // 8 float4 per A row
            int kq = q & 7;
            int gm = row0 + m;
            fa[i] = make_float4(0.f, 0.f, 0.f, 0.f);
            if (gm < M) fa[i] = ((const float4*)A)[(size_t)gm * K4 + kb4 + kq];
        }
        #pragma unroll
        for (int i = 0; i < BLOADS; i++) {
            int q  = tid + i * 256;
            int k  = q / (TN / 4);
            int nq = q % (TN / 4);
            fb[i] = ((const float4*)W)[(size_t)(kt * WKC + k) * (N >> 2) + (col0 >> 2) + nq];
        }
    };

    // ---- split-convert registers into smem stage st ----
    auto cvtstore = [&](int st) {
        #pragma unroll
        for (int i = 0; i < ALOADS; i++) {
            int q  = tid + i * 256;
            int m  = q >> 3;
            int kq = q & 7;
            float vv[4] = {fa[i].x, fa[i].y, fa[i].z, fa[i].w};
            #pragma unroll
            for (int c = 0; c < 4; c++) {
                float f = aSel ? fmaxf(vv[c], 0.f) : vv[c];
                __nv_bfloat16 h = __float2bfloat16(f);
                int idx = st * WTM * ALD + m * ALD + kq * 4 + c;
                Ah[idx] = h;
                Al[idx] = __float2bfloat16(f - __bfloat162float(h));
            }
        }
        #pragma unroll
        for (int i = 0; i < BLOADS; i++) {
            int q  = tid + i * 256;
            int k  = q / (TN / 4);
            int nq = q % (TN / 4);
            float vv[4] = {fb[i].x, fb[i].y, fb[i].z, fb[i].w};
            #pragma unroll
            for (int c = 0; c < 4; c++) {
                __nv_bfloat16 h = __float2bfloat16(vv[c]);
                int idx = st * WKC * BLD + k * BLD + nq * 4 + c;
                Bh[idx] = h;
                Bl[idx] = __float2bfloat16(vv[c] - __bfloat162float(h));
            }
        }
    };

    // ---- prologue ----
    fetch(0);
    cvtstore(0);
    __syncthreads();

    for (int t = 0; t < T; t++) {
        int st = t & 1;
        if (t + 1 < T) fetch(t + 1);   // global loads overlap with mma below
        #pragma unroll
        for (int kk = 0; kk < WKC; kk += 16) {
            wmma::fragment<wmma::matrix_a, 16, 16, 16, __nv_bfloat16, wmma::row_major> ah[2], al[2];
            wmma::fragment<wmma::matrix_b, 16, 16, 16, __nv_bfloat16, wmma::row_major> bh[FN], bl[FN];
            #pragma unroll
            for (int i = 0; i < 2; i++) {
                int base = st * WTM * ALD + (wm * 32 + i * 16) * ALD + kk;
                wmma::load_matrix_sync(ah[i], &Ah[base], ALD);
                wmma::load_matrix_sync(al[i], &Al[base], ALD);
            }
            #pragma unroll
            for (int j = 0; j < FN; j++) {
                int base = st * WKC * BLD + kk * BLD + wn * (TN / 2) + j * 16;
                wmma::load_matrix_sync(bh[j], &Bh[base], BLD);
                wmma::load_matrix_sync(bl[j], &Bl[base], BLD);
            }
            #pragma unroll
            for (int i = 0; i < 2; i++)
                #pragma unroll
                for (int j = 0; j < FN; j++) {
                    wmma::mma_sync(acc[i][j], ah[i], bh[j], acc[i][j]);
                    wmma::mma_sync(acc[i][j], ah[i], bl[j], acc[i][j]);
                    wmma::mma_sync(acc[i][j], al[i], bh[j], acc[i][j]);
                }
        }
        if (t + 1 < T) cvtstore((t + 1) & 1);
        __syncthreads();
    }

    #pragma unroll
    for (int i = 0; i < 2; i++) {
        int gm = row0 + wm * 32 + i * 16;   // may overrun into g_h pad rows (safe)
        #pragma unroll
        for (int j = 0; j < FN; j++)
            wmma::store_matrix_sync(&g_h[(size_t)gm * N + col0 + wn * (TN / 2) + j * 16],
                                    acc[i][j], N, wmma::mem_row_major);
    }
}

// ---------------- CSR gather: dst[n,f] = b[f] + h[n,f]*dinv[n]^2 + sum_e h[src]*norm ----------------
__global__ void k_gather(const float4* __restrict__ bias, float4* __restrict__ outp,
                         int toOut, int total /* Nn*F4 */, int F4mask, int lg) {
    int t = blockIdx.x * blockDim.x + threadIdx.x;
    if (t >= total) return;
    int node = t >> lg;
    int f = t & F4mask;
    const float4* h4 = (const float4*)g_h;
    float d = g_dinv[node];
    float s0 = d * d;
    float4 acc = bias[f];
    float4 v = h4[((size_t)node << lg) + f];
    acc.x = fmaf(v.x, s0, acc.x);
    acc.y = fmaf(v.y, s0, acc.y);
    acc.z = fmaf(v.z, s0, acc.z);
    acc.w = fmaf(v.w, s0, acc.w);

    int p   = g_rowptr[node];
    int end = g_rowptr[node + 1];
    for (; p + 3 < end; p += 4) {
        int2 m0 = g_csr[p];
        int2 m1 = g_csr[p + 1];
        int2 m2 = g_csr[p + 2];
        int2 m3 = g_csr[p + 3];
        float4 v0 = h4[((size_t)m0.x << lg) + f];
        float4 v1 = h4[((size_t)m1.x << lg) + f];
        float4 v2 = h4[((size_t)m2.x << lg) + f];
        float4 v3 = h4[((size_t)m3.x << lg) + f];
        float s1 = __int_as_float(m0.y);
        float s2 = __int_as_float(m1.y);
        float s3 = __int_as_float(m2.y);
        float s4 = __int_as_float(m3.y);
        acc.x = fmaf(v0.x, s1, acc.x); acc.y = fmaf(v0.y, s1, acc.y);
        acc.z = fmaf(v0.z, s1, acc.z); acc.w = fmaf(v0.w, s1, acc.w);
        acc.x = fmaf(v1.x, s2, acc.x); acc.y = fmaf(v1.y, s2, acc.y);
        acc.z = fmaf(v1.z, s2, acc.z); acc.w = fmaf(v1.w, s2, acc.w);
        acc.x = fmaf(v2.x, s3, acc.x); acc.y = fmaf(v2.y, s3, acc.y);
        acc.z = fmaf(v2.z, s3, acc.z); acc.w = fmaf(v2.w, s3, acc.w);
        acc.x = fmaf(v3.x, s4, acc.x); acc.y = fmaf(v3.y, s4, acc.y);
        acc.z = fmaf(v3.z, s4, acc.z); acc.w = fmaf(v3.w, s4, acc.w);
    }
    for (; p < end; p++) {
        int2 m0 = g_csr[p];
        float s1 = __int_as_float(m0.y);
        float4 v0 = h4[((size_t)m0.x << lg) + f];
        acc.x = fmaf(v0.x, s1, acc.x); acc.y = fmaf(v0.y, s1, acc.y);
        acc.z = fmaf(v0.z, s1, acc.z); acc.w = fmaf(v0.w, s1, acc.w);
    }
    float4* dst = toOut ? outp : (float4*)g_agg;
    dst[t] = acc;
}

// ---------------- host launch (single stream, capture-safe) ----------------
static inline int cdiv(long long a, int b) { return (int)((a + b - 1) / b); }

static inline int gemm_smem_bytes(int TN) {
    int ASZ = 2 * WTM * ALD;
    int BSZ = 2 * WKC * (TN + 8);
    return (2 * ASZ + 2 * BSZ) * 2;   // bf16 = 2 bytes
}

extern "C" void kernel_launch(void* const* d_in, const int* in_sizes, int n_in,
                              void* d_out, int out_size) {
    const float* x  = (const float*)d_in[0];
    const void*  ei = d_in[1];                 // int32 OR int64 — detected on device
    const float* W0 = (const float*)d_in[2];
    const float* b0 = (const float*)d_in[3];
    const float* W1 = (const float*)d_in[4];
    const float* b1 = (const float*)d_in[5];
    const float* W2 = (const float*)d_in[6];
    const float* b2 = (const float*)d_in[7];
    float* out = (float*)d_out;

    int F1 = in_sizes[3];              // 128
    int F0 = in_sizes[2] / F1;         // 256
    int F2 = in_sizes[5];              // 128
    int F3 = in_sizes[7];              // 64
    int Nn = in_sizes[0] / F0;         // 50000
    int E  = in_sizes[1] / 2;          // 800000

    // Opt-in to >48KB dynamic smem (host-side attribute; no device work).
    cudaFuncSetAttribute(k_gemm<128>, cudaFuncAttributeMaxDynamicSharedMemorySize,
                         gemm_smem_bytes(128));
    cudaFuncSetAttribute(k_gemm<64>,  cudaFuncAttributeMaxDynamicSharedMemorySize,
                         gemm_smem_bytes(64));

    // 0) dtype detect; degrees; dinv; scan; fused CSR build (one edge pass)
    k_detect    <<<1, 32>>>((const int*)ei);
    k_zero_deg  <<<cdiv(Nn, 256), 256>>>(Nn);
    k_count_deg <<<cdiv(E, 256), 256>>>(ei, E);
    k_dinv      <<<cdiv(Nn, 256), 256>>>(Nn);
    k_scan      <<<1, 1024>>>(Nn);
    k_build     <<<cdiv(E, 256), 256>>>(ei, E);

    // ---------- layer 1: x[Nn,F0] @ W0 -> F1 in g_h; gather -> g_agg ----------
    {
        int F4 = F1 / 4, lg = (F4 == 32) ? 5 : 4;
        dim3 grid(F1 / 128, cdiv(Nn, WTM));
        k_gemm<128><<<grid, 256, gemm_smem_bytes(128)>>>(x, W0, Nn, F0, F1, 0);
        k_gather<<<cdiv((long long)Nn * F4, 256), 256>>>(
            (const float4*)b0, (float4*)out, 0, Nn * F4, F4 - 1, lg);
    }

    // ---------- layer 2: relu(g_agg)[Nn,F1] @ W1 -> F2 in g_h; gather -> g_agg ----------
    {
        int F4 = F2 / 4, lg = (F4 == 32) ? 5 : 4;
        dim3 grid(F2 / 128, cdiv(Nn, WTM));
        k_gemm<128><<<grid, 256, gemm_smem_bytes(128)>>>(nullptr, W1, Nn, F1, F2, 1);
        k_gather<<<cdiv((long long)Nn * F4, 256), 256>>>(
            (const float4*)b1, (float4*)out, 0, Nn * F4, F4 - 1, lg);
    }

    // ---------- layer 3: relu(g_agg)[Nn,F2] @ W2 -> F3 in g_h; gather -> d_out ----------
    {
        int F4 = F3 / 4, lg = (F4 == 32) ? 5 : 4;
        dim3 grid(F3 / 64, cdiv(Nn, WTM));
        k_gemm<64><<<grid, 256, gemm_smem_bytes(64)>>>(nullptr, W2, Nn, F2, F3, 1);
        k_gather<<<cdiv((long long)Nn * F4, 256), 256>>>(
            (const float4*)b2, (float4*)out, 1, Nn * F4, F4 - 1, lg);
    }
    (void)n_in; (void)out_size;
}

// round 16
// speedup vs baseline: 1.3925x; 1.3925x over previous
#include <cuda_runtime.h>
#include <cuda_bf16.h>
#include <mma.h>
#include <cstdint>

using namespace nvcuda;

// Problem constants (fixed by the dataset)
#define MAX_N 50000
#define MAX_E 800000
#define MAX_F 128
#define MAX_K 256

// GEMM tiling (round-14 proven shape: 128x64 tile, single-buffered, 256 thr)
#define GTM 128
#define GTN 64
#define WKC 32
#define ALD 40             // A smem row stride (bf16, mult of 8)
#define BLD 72             // B smem row stride (bf16, mult of 8)

// ---------------- scratch (static device globals) ----------------
__device__ __align__(16) int   g_degi[MAX_N];
__device__ __align__(16) float g_dinv[MAX_N];
__device__ __align__(16) int   g_rowptr[MAX_N + 1];
__device__ __align__(16) int   g_cursor[MAX_N];
__device__ __align__(16) int2  g_csr [MAX_E];     // .x = src, .y = bits(norm)
// g_h padded by one M-tile of rows: unguarded wmma stores of the last partial
// tile land in scratch pad, never beyond this array.
__device__ __align__(16) float g_h   [(size_t)(MAX_N + GTM) * MAX_F];
// pre-split GEMM input (hi/lo bf16), written by k_xsplit (layer 1) or k_gather
__device__ __align__(16) __nv_bfloat16 g_ahi[(size_t)MAX_N * MAX_K];
__device__ __align__(16) __nv_bfloat16 g_alo[(size_t)MAX_N * MAX_K];
// pre-split weights, all 3 layers concatenated
__device__ __align__(16) __nv_bfloat16 g_whi[65536];
__device__ __align__(16) __nv_bfloat16 g_wlo[65536];
__device__ int g_is64;

// ---------------- helpers ----------------
__device__ __forceinline__ uint32_t pack2(__nv_bfloat16 a, __nv_bfloat16 b) {
    return (uint32_t)__bfloat16_as_ushort(a) | ((uint32_t)__bfloat16_as_ushort(b) << 16);
}

// split 4 floats -> hi uint2 + lo uint2 (memory order preserved)
__device__ __forceinline__ void split4(float a, float b, float c, float d,
                                       uint2& hi, uint2& lo) {
    __nv_bfloat16 h0 = __float2bfloat16(a), h1 = __float2bfloat16(b);
    __nv_bfloat16 h2 = __float2bfloat16(c), h3 = __float2bfloat16(d);
    hi.x = pack2(h0, h1); hi.y = pack2(h2, h3);
    lo.x = pack2(__float2bfloat16(a - __bfloat162float(h0)),
                 __float2bfloat16(b - __bfloat162float(h1)));
    lo.y = pack2(__float2bfloat16(c - __bfloat162float(h2)),
                 __float2bfloat16(d - __bfloat162float(h3)));
}

// ---------------- dtype detection: int64 vs int32 edge_index ----------------
__global__ void k_detect(const int* __restrict__ ei32) {
    if (threadIdx.x || blockIdx.x) return;
    int is64 = 1;
    #pragma unroll 1
    for (int i = 0; i < 128; i++) {
        if (ei32[2 * i + 1] != 0) { is64 = 0; break; }
    }
    g_is64 = is64;
}

__device__ __forceinline__ int edge_id(const void* ei, size_t pos) {
    if (g_is64) return (int)((const long long*)ei)[pos];
    return ((const int*)ei)[pos];
}

// ---------------- degree / norm precompute ----------------
__global__ void k_zero_deg(int n) {
    int i = blockIdx.x * blockDim.x + threadIdx.x;
    if (i < n) g_degi[i] = 0;
}

__global__ void k_count_deg(const void* __restrict__ ei, int E) {
    int e = blockIdx.x * blockDim.x + threadIdx.x;
    if (e < E) atomicAdd(&g_degi[edge_id(ei, (size_t)E + e)], 1);
}

__global__ void k_dinv(int n) {
    int i = blockIdx.x * blockDim.x + threadIdx.x;
    if (i < n) g_dinv[i] = rsqrtf((float)g_degi[i] + 1.0f);
}

// ---------------- exclusive prefix scan of degrees -> row_ptr (single block) ----------------
__global__ __launch_bounds__(1024) void k_scan(int Nn) {
    __shared__ int warp_sums[32];
    __shared__ int carry_sh;
    int tid  = threadIdx.x;
    int lane = tid & 31;
    int wid  = tid >> 5;
    if (tid == 0) carry_sh = 0;
    __syncthreads();
    for (int base = 0; base < Nn; base += 1024) {
        int i = base + tid;
        int v = (i < Nn) ? g_degi[i] : 0;
        int s = v;
        #pragma unroll
        for (int o = 1; o < 32; o <<= 1) {
            int t = __shfl_up_sync(0xFFFFFFFFu, s, o);
            if (lane >= o) s += t;
        }
        if (lane == 31) warp_sums[wid] = s;
        __syncthreads();
        if (wid == 0) {
            int ws = warp_sums[lane];
            #pragma unroll
            for (int o = 1; o < 32; o <<= 1) {
                int t = __shfl_up_sync(0xFFFFFFFFu, ws, o);
                if (lane >= o) ws += t;
            }
            warp_sums[lane] = ws;   // inclusive over warps
        }
        __syncthreads();
        int warp_off = (wid == 0) ? 0 : warp_sums[wid - 1];
        int excl = carry_sh + warp_off + (s - v);
        if (i < Nn) { g_rowptr[i] = excl; g_cursor[i] = excl; }
        __syncthreads();
        if (tid == 0) carry_sh += warp_sums[31];
        __syncthreads();
    }
    if (tid == 0) g_rowptr[Nn] = carry_sh;
}

// ---------------- CSR build: one pass over edges -> counting-sorted CSR ----------------
__global__ void k_build(const void* __restrict__ ei, int E) {
    int e = blockIdx.x * blockDim.x + threadIdx.x;
    if (e >= E) return;
    int s = edge_id(ei, e);
    int d = edge_id(ei, (size_t)E + e);
    float nrm = g_dinv[s] * g_dinv[d];
    int pos = atomicAdd(&g_cursor[d], 1);
    int2 m;
    m.x = s;
    m.y = __float_as_int(nrm);
    g_csr[pos] = m;
}

// ---------------- weight split: all three layers in one launch ----------------
__global__ void k_wsplit(const float* __restrict__ W0, const float* __restrict__ W1,
                         const float* __restrict__ W2, int n0, int n1, int n2) {
    int i = blockIdx.x * blockDim.x + threadIdx.x;
    if (i >= n0 + n1 + n2) return;
    float v = (i < n0) ? W0[i] : (i < n0 + n1 ? W1[i - n0] : W2[i - n0 - n1]);
    __nv_bfloat16 h = __float2bfloat16(v);
    g_whi[i] = h;
    g_wlo[i] = __float2bfloat16(v - __bfloat162float(h));
}

// ---------------- x split (layer-1 input, no relu) ----------------
__global__ void k_xsplit(const float4* __restrict__ x, int total /* Nn*K/4 */) {
    int i = blockIdx.x * blockDim.x + threadIdx.x;
    if (i >= total) return;
    float4 v = x[i];
    uint2 hi, lo;
    split4(v.x, v.y, v.z, v.w, hi, lo);
    ((uint2*)g_ahi)[i] = hi;
    ((uint2*)g_alo)[i] = lo;
}

// ---------------- GEMM: g_h[M,N] = A @ W (pre-split bf16 hi/lo, fp32 acc) ----
// acc += Ahi*Whi + Ahi*Wlo + Alo*Whi. 8 warps (4x2), warp tile 32x32.
__global__ __launch_bounds__(256) void k_gemm(int woff, int M, int K, int N) {
    __shared__ __nv_bfloat16 Ah[GTM][ALD];
    __shared__ __nv_bfloat16 Al[GTM][ALD];
    __shared__ __nv_bfloat16 Bh[WKC][BLD];
    __shared__ __nv_bfloat16 Bl[WKC][BLD];
    int tid  = threadIdx.x;
    int warp = tid >> 5;
    int wm   = warp >> 1;            // 0..3
    int wn   = warp & 1;             // 0..1
    int row0 = blockIdx.y * GTM;
    int col0 = blockIdx.x * GTN;

    wmma::fragment<wmma::accumulator, 16, 16, 16, float> acc[2][2];
    #pragma unroll
    for (int i = 0; i < 2; i++)
        #pragma unroll
        for (int j = 0; j < 2; j++)
            wmma::fill_fragment(acc[i][j], 0.0f);

    const uint4 z4 = make_uint4(0, 0, 0, 0);
    for (int k0 = 0; k0 < K; k0 += WKC) {
        // A tile: 128 rows x 32 k; hi+lo. 512 uint4 (8 bf16) per half; 2/thread.
        #pragma unroll
        for (int i = 0; i < 2; i++) {
            int q  = tid + i * 256;      // 0..511
            int m  = q >> 2;             // row
            int kq = q & 3;              // uint4 chunk along k
            int gm = row0 + m;
            uint4 vh = z4, vl = z4;
            if (gm < M) {
                size_t gi = ((size_t)gm * K + k0 + kq * 8) >> 3;
                vh = ((const uint4*)g_ahi)[gi];
                vl = ((const uint4*)g_alo)[gi];
            }
            *(uint4*)&Ah[m][kq * 8] = vh;
            *(uint4*)&Al[m][kq * 8] = vl;
        }
        // B tile: 32 k x 64 n; 256 uint4 per half; 1/thread.
        {
            int k  = tid >> 3;           // 0..31
            int nq = tid & 7;            // uint4 chunk along n
            size_t gi = ((size_t)woff + (size_t)(k0 + k) * N + col0 + nq * 8) >> 3;
            *(uint4*)&Bh[k][nq * 8] = ((const uint4*)g_whi)[gi];
            *(uint4*)&Bl[k][nq * 8] = ((const uint4*)g_wlo)[gi];
        }
        __syncthreads();
        #pragma unroll
        for (int kk = 0; kk < WKC; kk += 16) {
            wmma::fragment<wmma::matrix_a, 16, 16, 16, __nv_bfloat16, wmma::row_major> ah[2], al[2];
            wmma::fragment<wmma::matrix_b, 16, 16, 16, __nv_bfloat16, wmma::row_major> bh[2], bl[2];
            #pragma unroll
            for (int i = 0; i < 2; i++) {
                wmma::load_matrix_sync(ah[i], &Ah[wm * 32 + i * 16][kk], ALD);
                wmma::load_matrix_sync(al[i], &Al[wm * 32 + i * 16][kk], ALD);
            }
            #pragma unroll
            for (int j = 0; j < 2; j++) {
                wmma::load_matrix_sync(bh[j], &Bh[kk][wn * 32 + j * 16], BLD);
                wmma::load_matrix_sync(bl[j], &Bl[kk][wn * 32 + j * 16], BLD);
            }
            #pragma unroll
            for (int i = 0; i < 2; i++)
                #pragma unroll
                for (int j = 0; j < 2; j++) {
                    wmma::mma_sync(acc[i][j], ah[i], bh[j], acc[i][j]);
                    wmma::mma_sync(acc[i][j], ah[i], bl[j], acc[i][j]);
                    wmma::mma_sync(acc[i][j], al[i], bh[j], acc[i][j]);
                }
        }
        __syncthreads();
    }
    #pragma unroll
    for (int i = 0; i < 2; i++) {
        int gm = row0 + wm * 32 + i * 16;   // may overrun into g_h pad rows (safe)
        #pragma unroll
        for (int j = 0; j < 2; j++)
            wmma::store_matrix_sync(&g_h[(size_t)gm * N + col0 + wn * 32 + j * 16],
                                    acc[i][j], N, wmma::mem_row_major);
    }
}

// ---------------- CSR gather ----------------
// acc[n,f] = b[f] + h[n,f]*dinv[n]^2 + sum_e h[src]*norm
// toOut=1: write fp32 to outp (final layer).
// toOut=0: write relu(acc) split into g_ahi/g_alo (next layer's GEMM input).
__global__ void k_gather(const float4* __restrict__ bias, float4* __restrict__ outp,
                         int toOut, int total /* Nn*F4 */, int F4mask, int lg) {
    int t = blockIdx.x * blockDim.x + threadIdx.x;
    if (t >= total) return;
    int node = t >> lg;
    int f = t & F4mask;
    const float4* h4 = (const float4*)g_h;
    float d = g_dinv[node];
    float s0 = d * d;
    float4 acc = bias[f];
    float4 v = h4[((size_t)node << lg) + f];
    acc.x = fmaf(v.x, s0, acc.x);
    acc.y = fmaf(v.y, s0, acc.y);
    acc.z = fmaf(v.z, s0, acc.z);
    acc.w = fmaf(v.w, s0, acc.w);

    int p   = g_rowptr[node];
    int end = g_rowptr[node + 1];
    for (; p + 3 < end; p += 4) {
        int2 m0 = g_csr[p];
        int2 m1 = g_csr[p + 1];
        int2 m2 = g_csr[p + 2];
        int2 m3 = g_csr[p + 3];
        float4 v0 = h4[((size_t)m0.x << lg) + f];
        float4 v1 = h4[((size_t)m1.x << lg) + f];
        float4 v2 = h4[((size_t)m2.x << lg) + f];
        float4 v3 = h4[((size_t)m3.x << lg) + f];
        float s1 = __int_as_float(m0.y);
        float s2 = __int_as_float(m1.y);
        float s3 = __int_as_float(m2.y);
        float s4 = __int_as_float(m3.y);
        acc.x = fmaf(v0.x, s1, acc.x); acc.y = fmaf(v0.y, s1, acc.y);
        acc.z = fmaf(v0.z, s1, acc.z); acc.w = fmaf(v0.w, s1, acc.w);
        acc.x = fmaf(v1.x, s2, acc.x); acc.y = fmaf(v1.y, s2, acc.y);
        acc.z = fmaf(v1.z, s2, acc.z); acc.w = fmaf(v1.w, s2, acc.w);
        acc.x = fmaf(v2.x, s3, acc.x); acc.y = fmaf(v2.y, s3, acc.y);
        acc.z = fmaf(v2.z, s3, acc.z); acc.w = fmaf(v2.w, s3, acc.w);
        acc.x = fmaf(v3.x, s4, acc.x); acc.y = fmaf(v3.y, s4, acc.y);
        acc.z = fmaf(v3.z, s4, acc.z); acc.w = fmaf(v3.w, s4, acc.w);
    }
    for (; p < end; p++) {
        int2 m0 = g_csr[p];
        float s1 = __int_as_float(m0.y);
        float4 v0 = h4[((size_t)m0.x << lg) + f];
        acc.x = fmaf(v0.x, s1, acc.x); acc.y = fmaf(v0.y, s1, acc.y);
        acc.z = fmaf(v0.z, s1, acc.z); acc.w = fmaf(v0.w, s1, acc.w);
    }
    if (toOut) {
        outp[t] = acc;
    } else {
        uint2 hi, lo;
        split4(fmaxf(acc.x, 0.f), fmaxf(acc.y, 0.f),
               fmaxf(acc.z, 0.f), fmaxf(acc.w, 0.f), hi, lo);
        ((uint2*)g_ahi)[t] = hi;
        ((uint2*)g_alo)[t] = lo;
    }
}

// ---------------- host launch (single stream, capture-safe) ----------------
static inline int cdiv(long long a, int b) { return (int)((a + b - 1) / b); }

extern "C" void kernel_launch(void* const* d_in, const int* in_sizes, int n_in,
                              void* d_out, int out_size) {
    const float* x  = (const float*)d_in[0];
    const void*  ei = d_in[1];                 // int32 OR int64 — detected on device
    const float* W0 = (const float*)d_in[2];
    const float* b0 = (const float*)d_in[3];
    const float* W1 = (const float*)d_in[4];
    const float* b1 = (const float*)d_in[5];
    const float* W2 = (const float*)d_in[6];
    const float* b2 = (const float*)d_in[7];
    float* out = (float*)d_out;

    int F1 = in_sizes[3];              // 128
    int F0 = in_sizes[2] / F1;         // 256
    int F2 = in_sizes[5];              // 128
    int F3 = in_sizes[7];              // 64
    int Nn = in_sizes[0] / F0;         // 50000
    int E  = in_sizes[1] / 2;          // 800000
    int n0 = F0 * F1, n1 = F1 * F2, n2 = F2 * F3;

    // prep: dtype detect; degrees; dinv; scan; fused CSR build
    k_detect    <<<1, 32>>>((const int*)ei);
    k_zero_deg  <<<cdiv(Nn, 256), 256>>>(Nn);
    k_count_deg <<<cdiv(E, 256), 256>>>(ei, E);
    k_dinv      <<<cdiv(Nn, 256), 256>>>(Nn);
    k_scan      <<<1, 1024>>>(Nn);
    k_build     <<<cdiv(E, 256), 256>>>(ei, E);

    // one-time splits: weights (all layers) + layer-1 input
    k_wsplit<<<cdiv(n0 + n1 + n2, 256), 256>>>(W0, W1, W2, n0, n1, n2);
    k_xsplit<<<cdiv((long long)Nn * F0 / 4, 256), 256>>>((const float4*)x, Nn * F0 / 4);

    // ---------- layer 1: split(x) @ W0 -> g_h; gather -> split -> g_ahi/g_alo ----------
    {
        int F4 = F1 / 4, lg = (F4 == 32) ? 5 : 4;
        dim3 grid(F1 / GTN, cdiv(Nn, GTM));
        k_gemm<<<grid, 256>>>(0, Nn, F0, F1);
        k_gather<<<cdiv((long long)Nn * F4, 256), 256>>>(
            (const float4*)b0, (float4*)out, 0, Nn * F4, F4 - 1, lg);
    }

    // ---------- layer 2 ----------
    {
        int F4 = F2 / 4, lg = (F4 == 32) ? 5 : 4;
        dim3 grid(F2 / GTN, cdiv(Nn, GTM));
        k_gemm<<<grid, 256>>>(n0, Nn, F1, F2);
        k_gather<<<cdiv((long long)Nn * F4, 256), 256>>>(
            (const float4*)b1, (float4*)out, 0, Nn * F4, F4 - 1, lg);
    }

    // ---------- layer 3 (gather writes fp32 d_out) ----------
    {
        int F4 = F3 / 4, lg = (F4 == 32) ? 5 : 4;
        dim3 grid(F3 / GTN, cdiv(Nn, GTM));
        k_gemm<<<grid, 256>>>(n0 + n1, Nn, F2, F3);
        k_gather<<<cdiv((long long)Nn * F4, 256), 256>>>(
            (const float4*)b2, (float4*)out, 1, Nn * F4, F4 - 1, lg);
    }
    (void)n_in; (void)out_size;
}